// round 6
// baseline (speedup 1.0000x reference)
#include <cuda_runtime.h>

#define VOCAB 32
#define UTT_LEN 16
#define NTYPES 5
#define MPT 10
#define SUPPORT 100000
#define BATCH 2048
#define ENTRIES (SUPPORT * UTT_LEN)        // 1,600,000

#define NBLK 592                           // 4 blocks x 148 SMs, all resident
#define DEC_WARPS 3
#define KNN_WARPS 5
#define DW_TOTAL (NBLK * DEC_WARPS)        // 1776 decode warps
#define UNIT_ENTRIES 160                   // 5 warp-iters of 32 entries
#define UNITS (ENTRIES / UNIT_ENTRIES)     // 10000
#define SEGS 20
#define UNITS_PER_SEG (UNITS / SEGS)       // 500
#define SEG_ROWS (SUPPORT / SEGS)          // 5000 rows (80000B: 128B aligned)
#define TASK_ROWS 2500                     // half-segment per knn task
#define HALVES (SUPPORT / TASK_ROWS)       // 40
#define NGROUPS (BATCH / 32)               // 64
#define TASKS (NGROUPS * HALVES)           // 2560
#define KNN_LANES (KNN_WARPS * 32)         // 160
#define STEPS 16                           // 15*160 + 100 = 2500
#define LAST_LIM 100

// persistent scratch (no cudaMalloc allowed)
__device__ unsigned char g_packed[ENTRIES];   // token*4 per position
__device__ unsigned int  g_keys[BATCH];       // (cnt<<17)|(131071-row); monotone
                                              // fixed point -> no per-launch reset
__device__ unsigned int  g_segcnt[SEGS];      // decode progress; reset by out_kernel

__device__ __forceinline__ void fa(unsigned a, unsigned b, unsigned c,
                                   unsigned& s, unsigned& cy) {
    s  = a ^ b ^ c;                       // LOP3 0x96
    cy = (a & b) | (a & c) | (b & c);     // LOP3 0xE8
}
__device__ __forceinline__ void ha(unsigned a, unsigned b,
                                   unsigned& s, unsigned& cy) {
    s = a ^ b; cy = a & b;
}

// ---------------------------------------------------------------------------
// Fused persistent kernel: warps 0-2 decode (DRAM-bound), warps 3-7 knn
// (issue-bound). Co-resident on every SM so the two resource profiles overlap.
// Decode warps never wait on knn -> deadlock-free regardless of scheduling.
// ---------------------------------------------------------------------------
__global__ void __launch_bounds__(256, 4) fused_kernel(
        const float* __restrict__ support,
        const void* __restrict__ uttsv) {
    __shared__ unsigned tbl[UTT_LEN * VOCAB];  // tbl[m*32+v]: bit q = (tok_q[m]==v)

    const unsigned warp = threadIdx.x >> 5;
    const unsigned lane = threadIdx.x & 31;

    if (warp < DEC_WARPS) {
        // ------------------------- DECODE ROLE ------------------------------
        const unsigned dw = blockIdx.x * DEC_WARPS + warp;
        const int myr = (int)(lane >> 2);         // round holding my entry
        const int sh  = (int)(lane & 3) * 8;      // byte of my entry in ballots
        for (unsigned u = dw; u < UNITS; u += DW_TOTAL) {
            const unsigned ebase = u * UNIT_ENTRIES;
#pragma unroll
            for (int it = 0; it < 5; it++) {
                const unsigned base = ebase + it * 32;
                const float4* p = reinterpret_cast<const float4*>(support)
                                  + (size_t)base * 8;
                float4 vv[8];                      // front-batched: MLP=8
#pragma unroll
                for (int r = 0; r < 8; r++) vv[r] = __ldcs(p + r * 32 + lane);
                unsigned mysub = 0;
#pragma unroll
                for (int r = 0; r < 8; r++) {
                    unsigned bx = __ballot_sync(0xffffffffu, vv[r].x != 0.0f);
                    unsigned by = __ballot_sync(0xffffffffu, vv[r].y != 0.0f);
                    unsigned bz = __ballot_sync(0xffffffffu, vv[r].z != 0.0f);
                    unsigned bw = __ballot_sync(0xffffffffu, vv[r].w != 0.0f);
                    unsigned sub = ((bx >> sh) & 0xFFu)
                                 | (((by >> sh) & 0xFFu) << 8)
                                 | (((bz >> sh) & 0xFFu) << 16)
                                 | (((bw >> sh) & 0xFFu) << 24);
                    if (r == myr) mysub = sub;
                }
                int b = __ffs(mysub) - 1;
                int v = ((b & 7) << 2) | (b >> 3);
                g_packed[base + lane] = (unsigned char)(v << 2);  // pre-scaled x4
            }
            __threadfence();                       // publish writes
            if (lane == 0) atomicAdd(&g_segcnt[u / UNITS_PER_SEG], 1u);
        }
    } else {
        // --------------------------- KNN ROLE -------------------------------
        // local dtype detection (int64 -> odd 32-bit words of first 128 pairs 0)
        const int* u32p = (const int*)uttsv;
        bool nzd = false;
#pragma unroll
        for (int r = 0; r < 4; r++) nzd |= (u32p[(lane * 4 + r) * 2 + 1] != 0);
        const bool is64 = (__ballot_sync(0xffffffffu, nzd) == 0);
        const long long* u64p = (const long long*)uttsv;

        const unsigned kw  = warp - DEC_WARPS;     // 0..4
        const unsigned idx = kw * 32 + lane;       // 0..159

        unsigned tb[8];
#pragma unroll
        for (int p = 0; p < 8; p++) tb[p] = (idx & (1u << p)) ? 0xffffffffu : 0u;

        for (unsigned t = blockIdx.x; t < TASKS; t += NBLK) {
            const unsigned group   = t & (NGROUPS - 1);
            const unsigned half    = t >> 6;
            const unsigned seg     = half >> 1;
            const unsigned rowBase = half * TASK_ROWS;

            // wait for decode of this segment (decode warps keep making progress)
            while (((volatile unsigned*)g_segcnt)[seg] < UNITS_PER_SEG)
                __nanosleep(128);
            __threadfence();                       // acquire

            asm volatile("bar.sync 1, %0;" :: "n"(KNN_LANES) : "memory");
            for (unsigned j = idx; j < UTT_LEN * VOCAB; j += KNN_LANES) tbl[j] = 0u;
            asm volatile("bar.sync 1, %0;" :: "n"(KNN_LANES) : "memory");
            {   // build query-mask table via smem atomicOr (lane == query)
                const unsigned col = group * 32 + lane;
#pragma unroll
                for (int m = (int)kw; m < UTT_LEN; m += KNN_WARPS) {
                    int tok = is64 ? (int)u64p[(size_t)m * BATCH + col]
                                   : u32p[(size_t)m * BATCH + col];
                    atomicOr(&tbl[m * VOCAB + tok], 1u << lane);
                }
            }
            asm volatile("bar.sync 1, %0;" :: "n"(KNN_LANES) : "memory");

            const char* tbc = (const char*)tbl;
            const uint4* pk = reinterpret_cast<const uint4*>(g_packed)
                              + rowBase + idx;

            unsigned mx0 = 0, mx1 = 0, mx2 = 0, mx3 = 0, mx4 = 0;
            unsigned b0 = 0, b1 = 0, b2 = 0, b3 = 0;

#define STEP(I)                                                                   \
    do {                                                                          \
        uint4 pw = pk[(I) * KNN_LANES];                                           \
        unsigned l0  = *(const unsigned*)(tbc + 0 * 128  + __byte_perm(pw.x, 0, 0x4440)); \
        unsigned l1  = *(const unsigned*)(tbc + 1 * 128  + __byte_perm(pw.x, 0, 0x4441)); \
        unsigned l2  = *(const unsigned*)(tbc + 2 * 128  + __byte_perm(pw.x, 0, 0x4442)); \
        unsigned l3  = *(const unsigned*)(tbc + 3 * 128  + __byte_perm(pw.x, 0, 0x4443)); \
        unsigned l4  = *(const unsigned*)(tbc + 4 * 128  + __byte_perm(pw.y, 0, 0x4440)); \
        unsigned l5  = *(const unsigned*)(tbc + 5 * 128  + __byte_perm(pw.y, 0, 0x4441)); \
        unsigned l6  = *(const unsigned*)(tbc + 6 * 128  + __byte_perm(pw.y, 0, 0x4442)); \
        unsigned l7  = *(const unsigned*)(tbc + 7 * 128  + __byte_perm(pw.y, 0, 0x4443)); \
        unsigned l8  = *(const unsigned*)(tbc + 8 * 128  + __byte_perm(pw.z, 0, 0x4440)); \
        unsigned l9  = *(const unsigned*)(tbc + 9 * 128  + __byte_perm(pw.z, 0, 0x4441)); \
        unsigned l10 = *(const unsigned*)(tbc + 10 * 128 + __byte_perm(pw.z, 0, 0x4442)); \
        unsigned l11 = *(const unsigned*)(tbc + 11 * 128 + __byte_perm(pw.z, 0, 0x4443)); \
        unsigned l12 = *(const unsigned*)(tbc + 12 * 128 + __byte_perm(pw.w, 0, 0x4440)); \
        unsigned l13 = *(const unsigned*)(tbc + 13 * 128 + __byte_perm(pw.w, 0, 0x4441)); \
        unsigned l14 = *(const unsigned*)(tbc + 14 * 128 + __byte_perm(pw.w, 0, 0x4442)); \
        unsigned l15 = *(const unsigned*)(tbc + 15 * 128 + __byte_perm(pw.w, 0, 0x4443)); \
        unsigned s0, c0, s1, c1, s2, c2, s3, c3, s4, c4;                          \
        fa(l0, l1, l2, s0, c0);                                                   \
        fa(l3, l4, l5, s1, c1);                                                   \
        fa(l6, l7, l8, s2, c2);                                                   \
        fa(l9, l10, l11, s3, c3);                                                 \
        fa(l12, l13, l14, s4, c4);                                                \
        unsigned t0, d0, t1, d1;                                                  \
        fa(s0, s1, s2, t0, d0);                                                   \
        fa(s3, s4, l15, t1, d1);                                                  \
        unsigned n0, e0; ha(t0, t1, n0, e0);                                      \
        unsigned f0, g0, f1, g1, f2, g2;                                          \
        fa(c0, c1, c2, f0, g0);                                                   \
        fa(c3, c4, d0, f1, g1);                                                   \
        fa(f0, f1, d1, f2, g2);                                                   \
        unsigned n1, g3; ha(f2, e0, n1, g3);                                      \
        unsigned h0, k0; fa(g0, g1, g2, h0, k0);                                  \
        unsigned n2, k1; ha(h0, g3, n2, k1);                                      \
        unsigned n3, n4; ha(k0, k1, n3, n4);                                      \
        unsigned gt = n0 & ~mx0;                                                  \
        gt = (n1 & ~mx1) | (~(n1 ^ mx1) & gt);                                    \
        gt = (n2 & ~mx2) | (~(n2 ^ mx2) & gt);                                    \
        gt = (n3 & ~mx3) | (~(n3 ^ mx3) & gt);                                    \
        gt = (n4 & ~mx4) | (~(n4 ^ mx4) & gt);                                    \
        mx0 = (n0 & gt) | (mx0 & ~gt);                                            \
        mx1 = (n1 & gt) | (mx1 & ~gt);                                            \
        mx2 = (n2 & gt) | (mx2 & ~gt);                                            \
        mx3 = (n3 & gt) | (mx3 & ~gt);                                            \
        mx4 = (n4 & gt) | (mx4 & ~gt);                                            \
        if ((I) & 1) b0 |= gt; else b0 &= ~gt;                                    \
        if ((I) & 2) b1 |= gt; else b1 &= ~gt;                                    \
        if ((I) & 4) b2 |= gt; else b2 &= ~gt;                                    \
        if ((I) & 8) b3 |= gt; else b3 &= ~gt;                                    \
    } while (0)

            STEP(0);  STEP(1);  STEP(2);  STEP(3);
            STEP(4);  STEP(5);  STEP(6);  STEP(7);
            STEP(8);  STEP(9);  STEP(10); STEP(11);
            STEP(12); STEP(13); STEP(14);
            if (idx < LAST_LIM) STEP(15);
#undef STEP

            // planes: local row key v' = [step(4) | idx(8)]; order == row order
            unsigned mx[5] = {mx0, mx1, mx2, mx3, mx4};
            unsigned bi[12];
#pragma unroll
            for (int p = 0; p < 8; p++) bi[p] = tb[p];
            bi[8] = b0; bi[9] = b1; bi[10] = b2; bi[11] = b3;

            // warp butterfly merge of (cnt desc, row asc), bit-sliced
#pragma unroll
            for (int k = 1; k < 32; k <<= 1) {
                unsigned o[5], q[12];
#pragma unroll
                for (int p = 0; p < 5; p++)  o[p] = __shfl_xor_sync(0xffffffffu, mx[p], k);
#pragma unroll
                for (int p = 0; p < 12; p++) q[p] = __shfl_xor_sync(0xffffffffu, bi[p], k);
                unsigned gtc = mx[0] & ~o[0];
#pragma unroll
                for (int p = 1; p < 5; p++)
                    gtc = (mx[p] & ~o[p]) | (~(mx[p] ^ o[p]) & gtc);
                unsigned orx = 0;
#pragma unroll
                for (int p = 0; p < 5; p++) orx |= mx[p] ^ o[p];
                unsigned lt = ~bi[0] & q[0];
#pragma unroll
                for (int p = 1; p < 12; p++)
                    lt = (~bi[p] & q[p]) | (~(bi[p] ^ q[p]) & lt);
                unsigned tm = gtc | (lt & ~orx);
#pragma unroll
                for (int p = 0; p < 5; p++)  mx[p] = (mx[p] & tm) | (o[p] & ~tm);
#pragma unroll
                for (int p = 0; p < 12; p++) bi[p] = (bi[p] & tm) | (q[p] & ~tm);
            }

            unsigned cnt = 0, lr = 0;
#pragma unroll
            for (int p = 0; p < 5; p++)  cnt |= ((mx[p] >> lane) & 1u) << p;
#pragma unroll
            for (int p = 0; p < 12; p++) lr  |= ((bi[p] >> lane) & 1u) << p;
            unsigned row = rowBase + (lr >> 8) * KNN_LANES + (lr & 0xFFu);
            unsigned key = (cnt << 17) | (131071u - row);
            atomicMax(&g_keys[group * 32 + lane], key);
        }
    }
}

// ---------------------------------------------------------------------------
// out_kernel: gather meanings of the winner, emit one-hot, reset seg counters
// for the next graph replay (stream-ordered after fused_kernel).
// ---------------------------------------------------------------------------
__global__ void out_kernel(const void* __restrict__ meanv, float* __restrict__ out) {
    if (blockIdx.x == 0 && threadIdx.x < SEGS) g_segcnt[threadIdx.x] = 0u;

    const int lane = threadIdx.x & 31;
    const int* m32 = (const int*)meanv;
    bool nzd = false;
#pragma unroll
    for (int r = 0; r < 4; r++) nzd |= (m32[(lane * 4 + r) * 2 + 1] != 0);
    const bool m64 = (__ballot_sync(0xffffffffu, nzd) == 0);

    int idx = blockIdx.x * blockDim.x + threadIdx.x;
    if (idx >= BATCH * NTYPES * MPT) return;
    int n = idx / (NTYPES * MPT);
    int r = idx % (NTYPES * MPT);
    int t = r / MPT;
    int c = r % MPT;
    unsigned key = __ldg(&g_keys[n]);
    int row = 131071 - (int)(key & 0x1FFFFu);
    long long mval = m64 ? __ldg((const long long*)meanv + (size_t)row * NTYPES + t)
                         : (long long)__ldg(m32 + (size_t)row * NTYPES + t);
    out[idx] = (mval == (long long)c) ? 1.0f : 0.0f;
}

extern "C" void kernel_launch(void* const* d_in, const int* in_sizes, int n_in,
                              void* d_out, int out_size) {
    const void*  utts     = d_in[0];                 // [16,2048] int64/int32
    const float* support  = (const float*)d_in[1];   // [100000,512] fp32 one-hot
    const void*  meanings = (const void*)d_in[2];    // [100000,5] int64/int32
    float* out = (float*)d_out;                      // [2048,5,10] fp32

    fused_kernel<<<NBLK, 256>>>(support, utts);
    out_kernel<<<(BATCH * NTYPES * MPT + 127) / 128, 128>>>(meanings, out);
}

// round 7
// speedup vs baseline: 2.2996x; 2.2996x over previous
#include <cuda_runtime.h>

#define VOCAB 32
#define UTT_LEN 16
#define NTYPES 5
#define MPT 10
#define SUPPORT 100000
#define BATCH 2048

#define NS 16                            // support chunks
#define CHUNK (SUPPORT / NS)             // 6250
#define TPB 256
#define FULL_ITERS (CHUNK / TPB)         // 24
#define TAIL (CHUNK - FULL_ITERS * TPB)  // 106
#define NGROUPS (BATCH / 32)             // 64

#define ENTRIES (SUPPORT * UTT_LEN)      // 1,600,000 (divisible by 32)

// scratch (no cudaMalloc allowed)
__device__ unsigned char g_packed[ENTRIES];           // token*4 per position
__device__ unsigned int  g_keys[BATCH];               // (cnt<<17)|(131071-row)
__device__ int g_u64, g_m64;                          // dtype flags

// ---------------------------------------------------------------------------
// Kernel 1 (fused): detect int width + zero keys + decode one-hot support.
// Warp-cooperative, fully coalesced: each warp owns 32 entries = 4KB
// contiguous. Round r: lanes load consecutive float4 (512B/instr = minimal
// 4 wavefronts) covering entries 4r..4r+3; ballots convert one-hot floats
// to bitmasks; lane l extracts the token of entry l.
// (R3-proven: 33.8us, DRAM 78% ~= 90% of LTS structural ceiling.)
// ---------------------------------------------------------------------------
__global__ void __launch_bounds__(256) decode_kernel(
        const float* __restrict__ support,
        const int* __restrict__ utts32,
        const int* __restrict__ mean32) {
    const unsigned tid  = blockIdx.x * blockDim.x + threadIdx.x;
    const unsigned lane = threadIdx.x & 31;

    // fused dtype detection (first warp). Values are small non-negative ints;
    // if int64 (LE), every odd 32-bit word of the first 128 pairs is 0.
    if (tid < 32) {
        bool unz = false, mnz = false;
        for (int i = (int)tid; i < 128; i += 32) {
            unz |= (utts32[2 * i + 1] != 0);
            mnz |= (mean32[2 * i + 1] != 0);
        }
        unsigned ub = __ballot_sync(0xffffffffu, unz);
        unsigned mb = __ballot_sync(0xffffffffu, mnz);
        if (tid == 0) { g_u64 = (ub == 0); g_m64 = (mb == 0); }
    }
    if (tid < BATCH) g_keys[tid] = 0u;

    const unsigned gwarp = tid >> 5;              // global warp id
    const unsigned base  = gwarp * 32;            // first entry of this warp
    if (base >= ENTRIES) return;

    const float4* p = reinterpret_cast<const float4*>(support) + (size_t)base * 8;
    const int myr = (int)(lane >> 2);             // round holding my entry
    const int sh  = (int)(lane & 3) * 8;          // byte of my entry in ballots

    unsigned mysub = 0;
#pragma unroll
    for (int r = 0; r < 8; r++) {
        float4 v = __ldcs(p + r * 32 + lane);     // 512B contiguous, streaming
        unsigned bx = __ballot_sync(0xffffffffu, v.x != 0.0f);
        unsigned by = __ballot_sync(0xffffffffu, v.y != 0.0f);
        unsigned bz = __ballot_sync(0xffffffffu, v.z != 0.0f);
        unsigned bw = __ballot_sync(0xffffffffu, v.w != 0.0f);
        unsigned sub = ((bx >> sh) & 0xFFu)
                     | (((by >> sh) & 0xFFu) << 8)
                     | (((bz >> sh) & 0xFFu) << 16)
                     | (((bw >> sh) & 0xFFu) << 24);
        if (r == myr) mysub = sub;
    }
    int b = __ffs(mysub) - 1;                     // bit index in submask
    int v = ((b & 7) << 2) | (b >> 3);            // vocab token
    g_packed[base + lane] = (unsigned char)(v << 2);  // pre-scaled x4
}

// ---------------------------------------------------------------------------
// Kernel 2: bit-sliced match counting + argmax (R3-exact body).
// ONLY change vs R3: __launch_bounds__(TPB, 6) caps regs at 42 so 6 blocks
// (48 warps, 75%) fit per SM instead of 5 — knn was occupancy/latency-bound
// (occ 33%, issue 53%). Any spill lands in the once-run merge epilogue.
// ---------------------------------------------------------------------------
__device__ __forceinline__ void fa(unsigned a, unsigned b, unsigned c,
                                   unsigned& s, unsigned& cy) {
    s  = a ^ b ^ c;                       // LOP3 0x96
    cy = (a & b) | (a & c) | (b & c);     // LOP3 0xE8
}
__device__ __forceinline__ void ha(unsigned a, unsigned b,
                                   unsigned& s, unsigned& cy) {
    s = a ^ b; cy = a & b;
}

__global__ void __launch_bounds__(TPB, 6) knn_kernel(const void* __restrict__ uttsv) {
    __shared__ unsigned tbl[UTT_LEN * VOCAB];  // tbl[m*32+v]: bit q = (tok_q[m]==v)

    const unsigned tid   = threadIdx.x;
    const unsigned lane  = tid & 31;
    const unsigned warp  = tid >> 5;
    const unsigned chunk = blockIdx.x;
    const unsigned group = blockIdx.y;

    // Parallel table build: each of the 8 warps handles 2 positions.
    {
        const int is64 = g_u64;
        const unsigned col = group * 32 + lane;
        const long long* u64p = (const long long*)uttsv;
        const int*       u32p = (const int*)uttsv;
#pragma unroll
        for (int mm = 0; mm < 2; mm++) {
            int m = (int)(warp * 2 + mm);
            int tok = is64 ? (int)u64p[(size_t)m * BATCH + col]
                           : u32p[(size_t)m * BATCH + col];
#pragma unroll
            for (int v = 0; v < VOCAB; v++) {
                unsigned bm = __ballot_sync(0xffffffffu, tok == v);
                if (lane == (unsigned)v) tbl[m * VOCAB + v] = bm;
            }
        }
    }
    __syncthreads();

    const unsigned rowBase = chunk * CHUNK;
    const uint4* pk = reinterpret_cast<const uint4*>(g_packed) + rowBase + tid;
    const char* tbc = (const char*)tbl;

    unsigned mx0 = 0, mx1 = 0, mx2 = 0, mx3 = 0, mx4 = 0;
    unsigned b0 = 0, b1 = 0, b2 = 0, b3 = 0, b4 = 0;

#define STEP(I)                                                                   \
    do {                                                                          \
        uint4 pw = pk[(I) * TPB];                                                 \
        unsigned l0  = *(const unsigned*)(tbc + 0 * 128  + __byte_perm(pw.x, 0, 0x4440)); \
        unsigned l1  = *(const unsigned*)(tbc + 1 * 128  + __byte_perm(pw.x, 0, 0x4441)); \
        unsigned l2  = *(const unsigned*)(tbc + 2 * 128  + __byte_perm(pw.x, 0, 0x4442)); \
        unsigned l3  = *(const unsigned*)(tbc + 3 * 128  + __byte_perm(pw.x, 0, 0x4443)); \
        unsigned l4  = *(const unsigned*)(tbc + 4 * 128  + __byte_perm(pw.y, 0, 0x4440)); \
        unsigned l5  = *(const unsigned*)(tbc + 5 * 128  + __byte_perm(pw.y, 0, 0x4441)); \
        unsigned l6  = *(const unsigned*)(tbc + 6 * 128  + __byte_perm(pw.y, 0, 0x4442)); \
        unsigned l7  = *(const unsigned*)(tbc + 7 * 128  + __byte_perm(pw.y, 0, 0x4443)); \
        unsigned l8  = *(const unsigned*)(tbc + 8 * 128  + __byte_perm(pw.z, 0, 0x4440)); \
        unsigned l9  = *(const unsigned*)(tbc + 9 * 128  + __byte_perm(pw.z, 0, 0x4441)); \
        unsigned l10 = *(const unsigned*)(tbc + 10 * 128 + __byte_perm(pw.z, 0, 0x4442)); \
        unsigned l11 = *(const unsigned*)(tbc + 11 * 128 + __byte_perm(pw.z, 0, 0x4443)); \
        unsigned l12 = *(const unsigned*)(tbc + 12 * 128 + __byte_perm(pw.w, 0, 0x4440)); \
        unsigned l13 = *(const unsigned*)(tbc + 13 * 128 + __byte_perm(pw.w, 0, 0x4441)); \
        unsigned l14 = *(const unsigned*)(tbc + 14 * 128 + __byte_perm(pw.w, 0, 0x4442)); \
        unsigned l15 = *(const unsigned*)(tbc + 15 * 128 + __byte_perm(pw.w, 0, 0x4443)); \
        unsigned s0, c0, s1, c1, s2, c2, s3, c3, s4, c4;                          \
        fa(l0, l1, l2, s0, c0);                                                   \
        fa(l3, l4, l5, s1, c1);                                                   \
        fa(l6, l7, l8, s2, c2);                                                   \
        fa(l9, l10, l11, s3, c3);                                                 \
        fa(l12, l13, l14, s4, c4);                                                \
        unsigned t0, d0, t1, d1;                                                  \
        fa(s0, s1, s2, t0, d0);                                                   \
        fa(s3, s4, l15, t1, d1);                                                  \
        unsigned n0, e0; ha(t0, t1, n0, e0);                                      \
        unsigned f0, g0, f1, g1, f2, g2;                                          \
        fa(c0, c1, c2, f0, g0);                                                   \
        fa(c3, c4, d0, f1, g1);                                                   \
        fa(f0, f1, d1, f2, g2);                                                   \
        unsigned n1, g3; ha(f2, e0, n1, g3);                                      \
        unsigned h0, k0; fa(g0, g1, g2, h0, k0);                                  \
        unsigned n2, k1; ha(h0, g3, n2, k1);                                      \
        unsigned n3, n4; ha(k0, k1, n3, n4);                                      \
        unsigned gt = n0 & ~mx0;                                                  \
        gt = (n1 & ~mx1) | (~(n1 ^ mx1) & gt);                                    \
        gt = (n2 & ~mx2) | (~(n2 ^ mx2) & gt);                                    \
        gt = (n3 & ~mx3) | (~(n3 ^ mx3) & gt);                                    \
        gt = (n4 & ~mx4) | (~(n4 ^ mx4) & gt);                                    \
        mx0 = (n0 & gt) | (mx0 & ~gt);                                            \
        mx1 = (n1 & gt) | (mx1 & ~gt);                                            \
        mx2 = (n2 & gt) | (mx2 & ~gt);                                            \
        mx3 = (n3 & gt) | (mx3 & ~gt);                                            \
        mx4 = (n4 & gt) | (mx4 & ~gt);                                            \
        if ((I) & 1)  b0 |= gt; else b0 &= ~gt;                                   \
        if ((I) & 2)  b1 |= gt; else b1 &= ~gt;                                   \
        if ((I) & 4)  b2 |= gt; else b2 &= ~gt;                                   \
        if ((I) & 8)  b3 |= gt; else b3 &= ~gt;                                   \
        if ((I) & 16) b4 |= gt; else b4 &= ~gt;                                   \
    } while (0)

    STEP(0);  STEP(1);  STEP(2);  STEP(3);  STEP(4);  STEP(5);
    STEP(6);  STEP(7);  STEP(8);  STEP(9);  STEP(10); STEP(11);
    STEP(12); STEP(13); STEP(14); STEP(15); STEP(16); STEP(17);
    STEP(18); STEP(19); STEP(20); STEP(21); STEP(22); STEP(23);
    if (tid < TAIL) STEP(24);
#undef STEP

    // Materialize full row planes: row = tid (8 bits) | iter (5 bits).
    unsigned mx[5] = {mx0, mx1, mx2, mx3, mx4};
    unsigned bi[13];
#pragma unroll
    for (int p = 0; p < 8; p++) bi[p] = (tid & (1u << p)) ? 0xffffffffu : 0u;
    bi[8] = b0; bi[9] = b1; bi[10] = b2; bi[11] = b3; bi[12] = b4;

    // Warp butterfly merge of (cnt desc, row asc), bit-sliced.
#pragma unroll
    for (int k = 1; k < 32; k <<= 1) {
        unsigned o[5], q[13];
#pragma unroll
        for (int p = 0; p < 5; p++)  o[p] = __shfl_xor_sync(0xffffffffu, mx[p], k);
#pragma unroll
        for (int p = 0; p < 13; p++) q[p] = __shfl_xor_sync(0xffffffffu, bi[p], k);
        unsigned gtc = mx[0] & ~o[0];
#pragma unroll
        for (int p = 1; p < 5; p++)
            gtc = (mx[p] & ~o[p]) | (~(mx[p] ^ o[p]) & gtc);
        unsigned orx = 0;
#pragma unroll
        for (int p = 0; p < 5; p++) orx |= mx[p] ^ o[p];    // ~orx = counts equal
        unsigned lt = ~bi[0] & q[0];
#pragma unroll
        for (int p = 1; p < 13; p++)
            lt = (~bi[p] & q[p]) | (~(bi[p] ^ q[p]) & lt);  // my row < partner row
        unsigned tm = gtc | (lt & ~orx);                    // keep mine
#pragma unroll
        for (int p = 0; p < 5; p++)  mx[p] = (mx[p] & tm) | (o[p] & ~tm);
#pragma unroll
        for (int p = 0; p < 13; p++) bi[p] = (bi[p] & tm) | (q[p] & ~tm);
    }

    // lane q extracts query q's (cnt,row) from the merged planes
    unsigned cnt = 0, lr = 0;
#pragma unroll
    for (int p = 0; p < 5; p++)  cnt |= ((mx[p] >> lane) & 1u) << p;
#pragma unroll
    for (int p = 0; p < 13; p++) lr  |= ((bi[p] >> lane) & 1u) << p;
    unsigned row = rowBase + lr;
    unsigned key = (cnt << 17) | (131071u - row);
    atomicMax(&g_keys[group * 32 + lane], key);
}

// ---------------------------------------------------------------------------
// Kernel 3: gather meanings of the winner and emit one-hot output.
// ---------------------------------------------------------------------------
__global__ void out_kernel(const void* __restrict__ meanv, float* __restrict__ out) {
    int idx = blockIdx.x * blockDim.x + threadIdx.x;
    if (idx >= BATCH * NTYPES * MPT) return;
    int n = idx / (NTYPES * MPT);
    int r = idx % (NTYPES * MPT);
    int t = r / MPT;
    int c = r % MPT;
    unsigned key = __ldg(&g_keys[n]);
    int row = 131071 - (int)(key & 0x1FFFFu);
    long long mval = g_m64 ? __ldg((const long long*)meanv + (size_t)row * NTYPES + t)
                           : (long long)__ldg((const int*)meanv + (size_t)row * NTYPES + t);
    out[idx] = (mval == (long long)c) ? 1.0f : 0.0f;
}

extern "C" void kernel_launch(void* const* d_in, const int* in_sizes, int n_in,
                              void* d_out, int out_size) {
    const void*  utts     = d_in[0];                 // [16,2048] int64/int32
    const float* support  = (const float*)d_in[1];   // [100000,512] fp32 one-hot
    const void*  meanings = (const void*)d_in[2];    // [100000,5] int64/int32
    float* out = (float*)d_out;                      // [2048,5,10] fp32

    // one warp per 32 entries: 1.6M entries -> 50000 warps -> 6250 blocks
    decode_kernel<<<(ENTRIES / 32 + 7) / 8, 256>>>(
        support, (const int*)utts, (const int*)meanings);
    dim3 grid(NS, NGROUPS);
    knn_kernel<<<grid, TPB>>>(utts);
    out_kernel<<<(BATCH * NTYPES * MPT + 127) / 128, 128>>>(meanings, out);
}